// round 3
// baseline (speedup 1.0000x reference)
#include <cuda_runtime.h>
#include <math.h>

#define NN   8192
#define DD   200
#define BB   4
#define EE   4096
#define DEG  16
#define HH   128
#define EPSf 1e-8f

// ---------------- scratch (device globals; no allocation allowed) ----------------
__device__ float g_out[NN * DD];      // x @ W
__device__ float g_hyper[NN * DD];    // L @ out
__device__ float g_Medge[EE * DD];
__device__ float g_gp[NN * HH];
__device__ float g_fused[NN * HH];
__device__ int   g_dv_cnt[NN];
__device__ int   g_cursor[NN];
__device__ int   g_de_cnt[EE];
__device__ unsigned g_maskbits[EE];
__device__ int   g_offsets[NN];
__device__ int   g_node_edges[EE * DEG];
__device__ float g_alpha_part[256];
__device__ float g_alpha;
__device__ float g_att[BB * HH];
__device__ float g_cvec[BB * HH];

// packed dual-fp32 FMA (SASS FFMA2) — only reachable via PTX f32x2
#define FMA_F32X2(acc, a, b) \
    asm("fma.rn.f32x2 %0, %1, %2, %0;" : "+l"(acc) : "l"(a), "l"(b))
#define PACK_DUP_F32X2(out, s) \
    asm("mov.b64 %0, {%1, %1};" : "=l"(out) : "r"(__float_as_uint(s)))

// ---------------- misc small kernels ----------------
__global__ void k_zero() {
    int i = blockIdx.x * blockDim.x + threadIdx.x;
    if (i < NN) { g_dv_cnt[i] = 0; g_cursor[i] = 0; }
}

__global__ void k_alpha_part(const float* __restrict__ x, const float* __restrict__ gw) {
    __shared__ float sm[256];
    int t = threadIdx.x;
    float s = 0.f;
    for (int i = blockIdx.x * 256 + t; i < NN * DD; i += 256 * 256)
        s += x[i] * gw[i % DD];
    sm[t] = s; __syncthreads();
    for (int o = 128; o > 0; o >>= 1) { if (t < o) sm[t] += sm[t + o]; __syncthreads(); }
    if (t == 0) g_alpha_part[blockIdx.x] = sm[0];
}

__global__ void k_alpha_fin(const float* __restrict__ gb) {
    __shared__ float sm[256];
    int t = threadIdx.x;
    sm[t] = g_alpha_part[t]; __syncthreads();
    for (int o = 128; o > 0; o >>= 1) { if (t < o) sm[t] += sm[t + o]; __syncthreads(); }
    if (t == 0) g_alpha = 1.f / (1.f + expf(-(sm[0] / (float)NN + gb[0])));
}

// ---------------- hypergraph sparse stages ----------------
__global__ void k_edge_a(const int* __restrict__ en) {
    int e = blockIdx.x * blockDim.x + threadIdx.x;
    if (e >= EE) return;
    int nd[DEG];
#pragma unroll
    for (int s = 0; s < DEG; s++) nd[s] = en[e * DEG + s];
    unsigned m = 0; int uniq = 0;
#pragma unroll
    for (int s = 0; s < DEG; s++) {
        bool first = true;
        for (int j = 0; j < s; j++) if (nd[j] == nd[s]) { first = false; break; }
        if (first) { m |= (1u << s); uniq++; atomicAdd(&g_dv_cnt[nd[s]], 1); }
    }
    g_maskbits[e] = m;
    g_de_cnt[e] = uniq;
}

__global__ void k_scan() {
    __shared__ int part[256];
    int t = threadIdx.x;
    int base = t * 32;
    int s = 0;
    for (int i = 0; i < 32; i++) s += g_dv_cnt[base + i];
    part[t] = s; __syncthreads();
    for (int off = 1; off < 256; off <<= 1) {
        int v = 0;
        if (t >= off) v = part[t - off];
        __syncthreads();
        part[t] += v;
        __syncthreads();
    }
    int run = (t == 0) ? 0 : part[t - 1];
    for (int i = 0; i < 32; i++) { g_offsets[base + i] = run; run += g_dv_cnt[base + i]; }
}

__global__ void k_fill(const int* __restrict__ en) {
    int e = blockIdx.x * blockDim.x + threadIdx.x;
    if (e >= EE) return;
    unsigned m = g_maskbits[e];
    for (int s = 0; s < DEG; s++) if ((m >> s) & 1u) {
        int n = en[e * DEG + s];
        int p = atomicAdd(&g_cursor[n], 1);
        g_node_edges[g_offsets[n] + p] = e;
    }
}

__global__ void k_sort() {
    int n = blockIdx.x * blockDim.x + threadIdx.x;
    if (n >= NN) return;
    int len = g_dv_cnt[n];
    int* a = &g_node_edges[g_offsets[n]];
    for (int i = 1; i < len; i++) {
        int key = a[i]; int j = i - 1;
        while (j >= 0 && a[j] > key) { a[j + 1] = a[j]; j--; }
        a[j + 1] = key;
    }
}

__global__ void k_edge_b(const int* __restrict__ en) {
    int e = blockIdx.x;
    __shared__ int   sn[DEG];
    __shared__ float sw[DEG];
    int t = threadIdx.x;
    if (t < DEG) {
        int n = en[e * DEG + t];
        sn[t] = n;
        sw[t] = ((g_maskbits[e] >> t) & 1u)
                  ? rsqrtf((float)g_dv_cnt[n] * (1.f / DEG) + EPSf) : 0.f;
    }
    __syncthreads();
    if (t >= DD / 4) return;
    float4 acc = make_float4(0.f, 0.f, 0.f, 0.f);
#pragma unroll
    for (int s = 0; s < DEG; s++) {
        float w = sw[s];
        float4 v = ((const float4*)&g_out[sn[s] * DD])[t];
        acc.x += w * v.x; acc.y += w * v.y; acc.z += w * v.z; acc.w += w * v.w;
    }
    float sc = 1.f / ((float)g_de_cnt[e] * (1.f / DEG) + EPSf) * (1.f / (DEG * DEG));
    ((float4*)&g_Medge[e * DD])[t] =
        make_float4(acc.x * sc, acc.y * sc, acc.z * sc, acc.w * sc);
}

__global__ void k_gather() {
    int n = blockIdx.x;
    int t = threadIdx.x;
    int len  = g_dv_cnt[n];
    int base = g_offsets[n];
    float dvn = rsqrtf((float)len * (1.f / DEG) + EPSf);
    if (t >= DD / 4) return;
    float4 acc = make_float4(0.f, 0.f, 0.f, 0.f);
    for (int i = 0; i < len; i++) {
        int e = g_node_edges[base + i];
        float4 v = ((const float4*)&g_Medge[e * DD])[t];
        acc.x += v.x; acc.y += v.y; acc.z += v.z; acc.w += v.w;
    }
    ((float4*)&g_hyper[n * DD])[t] =
        make_float4(acc.x * dvn, acc.y * dvn, acc.z * dvn, acc.w * dvn);
}

// ---------------- per-batch constants ----------------
__global__ void k_const(const float* __restrict__ text,
                        const float* __restrict__ text_w, const float* __restrict__ text_b,
                        const float* __restrict__ in_w,   const float* __restrict__ in_b,
                        const float* __restrict__ aow,    const float* __restrict__ aob,
                        const float* __restrict__ fgw,    const float* __restrict__ fgb) {
    __shared__ float tp[BB][HH];
    __shared__ float vv[BB][HH];
    __shared__ float at[BB][HH];
    int j = threadIdx.x;  // 128 threads
    for (int b = 0; b < BB; b++) {
        float s = text_b[j];
        for (int k = 0; k < DD; k++) s += text[b * DD + k] * text_w[k * HH + j];
        tp[b][j] = s;
    }
    __syncthreads();
    for (int b = 0; b < BB; b++) {
        float s = in_b[2 * HH + j];
        for (int k = 0; k < HH; k++) s += tp[b][k] * in_w[k * 3 * HH + 2 * HH + j];
        vv[b][j] = s;
    }
    __syncthreads();
    for (int b = 0; b < BB; b++) {
        float s = aob[j];
        for (int k = 0; k < HH; k++) s += vv[b][k] * aow[k * HH + j];
        at[b][j] = s;
        g_att[b * HH + j] = s;
    }
    __syncthreads();
    for (int b = 0; b < BB; b++) {
        float s = fgb[j];
        for (int k = 0; k < HH; k++) s += at[b][k] * fgw[(HH + k) * HH + j];
        g_cvec[b * HH + j] = s;
    }
}

// ---------------- SGEMM v3: 128x64 tile, 128 threads, 8x8/thread, FFMA2 ----------------
// thread map: tx = t&7 -> n = tx*8 (8 cols), ty = t>>3 -> m = ty*8 (8 rows)
// acc: 8 m-rows x 4 f32x2 (pairs along n)
#define AST 132   // AsT row stride (128 + 4)
#define BST 68    // Bs row stride (64 + 4)
template <int MODE>
__global__ void __launch_bounds__(128)
gemm3_k(const float* __restrict__ Aext, const float* __restrict__ Bm,
        float* __restrict__ Cext, int Ncols, int K,
        const float* __restrict__ bias, const float* __restrict__ avec) {
    const float* A = (MODE == 1) ? (const float*)g_out
                   : (MODE == 2) ? (const float*)g_gp
                   : (MODE == 3) ? (const float*)g_fused : Aext;
    float* C = (MODE == 0) ? (float*)g_out
             : (MODE == 1) ? (float*)g_gp
             : (MODE == 2) ? (float*)g_fused : Cext;

    __shared__ __align__(16) float AsT[2][16][AST];  // [k][m]
    __shared__ __align__(16) float Bs [2][16][BST];  // [k][n]

    const int t  = threadIdx.x;
    const int tx = t & 7;
    const int ty = t >> 3;
    const int m0 = blockIdx.y * 128;
    const int n0 = blockIdx.x * 64;

    float alpha = 0.f, beta = 0.f;
    if (MODE == 1) { alpha = g_alpha; beta = 1.f - alpha; }

    // A load mapping: 512 float4 per chunk, 4 per thread (i = c*128 + t)
    // row = i>>2, kq = (i&3)*4  -> coalesced 64B per 4 threads
    const int a_kq = (t & 3) * 4;
    // B load mapping: 256 float4, 2 per thread
    const int bIdx0 = 2 * t, bIdx1 = 2 * t + 1;
    const int bk0 = bIdx0 >> 4, bn0 = (bIdx0 & 15) * 4;
    const int bk1 = bIdx1 >> 4, bn1 = (bIdx1 & 15) * 4;

    const int KB = (K + 15) / 16;

    unsigned long long acc[8][4];
#pragma unroll
    for (int i = 0; i < 8; i++)
#pragma unroll
        for (int j = 0; j < 4; j++) acc[i][j] = 0ull;

    float4 ra[4], rb0, rb1;
    const float4 z4 = make_float4(0.f, 0.f, 0.f, 0.f);

    auto loadChunk = [&](int k0) {
#pragma unroll
        for (int c = 0; c < 4; c++) {
            int ar = (c * 128 + t) >> 2;          // row in tile
            int gk = k0 + a_kq;
            if (gk < K) {
                int base = (m0 + ar) * K + gk;
                if (MODE == 1) {
                    float4 o = *(const float4*)&A[base];
                    float4 h = *(const float4*)&g_hyper[base];
                    float4 av = *(const float4*)&avec[gk];
                    ra[c] = make_float4(alpha*o.x + beta*h.x + av.x,
                                        alpha*o.y + beta*h.y + av.y,
                                        alpha*o.z + beta*h.z + av.z,
                                        alpha*o.w + beta*h.w + av.w);
                } else ra[c] = *(const float4*)&A[base];
            } else ra[c] = z4;
        }
        int gk = k0 + bk0; int gn = n0 + bn0;
        rb0 = (gk < K && gn < Ncols) ? *(const float4*)&Bm[gk * Ncols + gn] : z4;
        gk = k0 + bk1; gn = n0 + bn1;
        rb1 = (gk < K && gn < Ncols) ? *(const float4*)&Bm[gk * Ncols + gn] : z4;
    };
    auto storeChunk = [&](int buf) {
#pragma unroll
        for (int c = 0; c < 4; c++) {
            int ar = (c * 128 + t) >> 2;
            AsT[buf][a_kq + 0][ar] = ra[c].x;
            AsT[buf][a_kq + 1][ar] = ra[c].y;
            AsT[buf][a_kq + 2][ar] = ra[c].z;
            AsT[buf][a_kq + 3][ar] = ra[c].w;
        }
        *(float4*)&Bs[buf][bk0][bn0] = rb0;
        *(float4*)&Bs[buf][bk1][bn1] = rb1;
    };

    loadChunk(0);
    storeChunk(0);
    __syncthreads();

    for (int kb = 0; kb < KB; kb++) {
        int buf = kb & 1;
        if (kb + 1 < KB) loadChunk((kb + 1) * 16);
#pragma unroll
        for (int kk = 0; kk < 16; kk++) {
            float4 a0 = *(const float4*)&AsT[buf][kk][ty * 8];
            float4 a1 = *(const float4*)&AsT[buf][kk][ty * 8 + 4];
            // b pairs: 4 x f32x2, loaded pre-packed from smem
            unsigned long long bp[4];
            {
                const unsigned long long* bq =
                    (const unsigned long long*)&Bs[buf][kk][tx * 8];
                bp[0] = bq[0]; bp[1] = bq[1]; bp[2] = bq[2]; bp[3] = bq[3];
            }
            float am[8] = {a0.x, a0.y, a0.z, a0.w, a1.x, a1.y, a1.z, a1.w};
#pragma unroll
            for (int i = 0; i < 8; i++) {
                unsigned long long ad;
                PACK_DUP_F32X2(ad, am[i]);
#pragma unroll
                for (int j = 0; j < 4; j++)
                    FMA_F32X2(acc[i][j], ad, bp[j]);
            }
        }
        if (kb + 1 < KB) storeChunk(buf ^ 1);
        __syncthreads();
    }

    // ---------------- epilogue ----------------
#pragma unroll
    for (int i = 0; i < 8; i++) {
        int r = m0 + ty * 8 + i;
        int cb = n0 + tx * 8;
        float v[8];
#pragma unroll
        for (int j = 0; j < 4; j++) {
            float2 p = *(float2*)&acc[i][j];
            v[2 * j] = p.x; v[2 * j + 1] = p.y;
        }
        if (MODE == 2) {
            int bi = r >> 11;  // Nn = 2048
            float4 gp0 = *(const float4*)&g_gp[r * HH + cb];
            float4 gp1 = *(const float4*)&g_gp[r * HH + cb + 4];
            float gpv[8] = {gp0.x, gp0.y, gp0.z, gp0.w, gp1.x, gp1.y, gp1.z, gp1.w};
#pragma unroll
            for (int j = 0; j < 8; j++) {
                int cidx = cb + j;
                float g = 1.f / (1.f + expf(-(v[j] + g_cvec[bi * HH + cidx])));
                float attv = g_att[bi * HH + cidx];
                v[j] = g * gpv[j] + (1.f - g) * attv;
            }
            *(float4*)&C[r * HH + cb]     = make_float4(v[0], v[1], v[2], v[3]);
            *(float4*)&C[r * HH + cb + 4] = make_float4(v[4], v[5], v[6], v[7]);
        } else {
#pragma unroll
            for (int q = 0; q < 2; q++) {
                int c0 = cb + q * 4;
                if (c0 < Ncols) {
                    float4 o;
                    if (MODE == 0) {
                        o = make_float4(v[q*4], v[q*4+1], v[q*4+2], v[q*4+3]);
                    } else {
                        float4 bi4 = *(const float4*)&bias[c0];
                        o = make_float4(v[q*4] + bi4.x, v[q*4+1] + bi4.y,
                                        v[q*4+2] + bi4.z, v[q*4+3] + bi4.w);
                    }
                    *(float4*)&C[r * Ncols + c0] = o;
                }
            }
        }
    }
}

// ---------------- launcher ----------------
extern "C" void kernel_launch(void* const* d_in, const int* in_sizes, int n_in,
                              void* d_out, int out_size) {
    const float* x      = (const float*)d_in[0];
    const float* text   = (const float*)d_in[1];
    const float* W      = (const float*)d_in[2];
    const float* bvec   = (const float*)d_in[3];
    const float* gate_w = (const float*)d_in[4];
    const float* gate_b = (const float*)d_in[5];
    const float* gnn_w  = (const float*)d_in[6];
    const float* gnn_b  = (const float*)d_in[7];
    const float* text_w = (const float*)d_in[8];
    const float* text_b = (const float*)d_in[9];
    const float* in_w   = (const float*)d_in[10];
    const float* in_b   = (const float*)d_in[11];
    const float* aow    = (const float*)d_in[12];
    const float* aob    = (const float*)d_in[13];
    const float* fgw    = (const float*)d_in[14];
    const float* fgb    = (const float*)d_in[15];
    const float* outp_w = (const float*)d_in[16];
    const float* outp_b = (const float*)d_in[17];
    const int*   en     = (const int*)d_in[18];
    float* outp = (float*)d_out;

    k_zero<<<32, 256>>>();
    k_alpha_part<<<256, 256>>>(x, gate_w);
    k_alpha_fin<<<1, 256>>>(gate_b);

    // out = x @ W
    gemm3_k<0><<<dim3(4, 64), 128>>>(x, W, nullptr, DD, DD, nullptr, nullptr);

    // hypergraph propagation
    k_edge_a<<<EE / 256, 256>>>(en);
    k_scan<<<1, 256>>>();
    k_fill<<<EE / 256, 256>>>(en);
    k_sort<<<NN / 256, 256>>>();
    k_edge_b<<<EE, 64>>>(en);
    k_gather<<<NN, 64>>>();

    // per-batch attention constants
    k_const<<<1, 128>>>(text, text_w, text_b, in_w, in_b, aow, aob, fgw, fgb);

    // gp = (alpha*out + (1-alpha)*hyper + b) @ gnn_w + gnn_b
    gemm3_k<1><<<dim3(2, 64), 128>>>(nullptr, gnn_w, nullptr, HH, DD, gnn_b, bvec);

    // fused = sigmoid(gp @ fgate_w[:H] + c[b]) * gp + (1-g) * att[b]
    gemm3_k<2><<<dim3(2, 64), 128>>>(nullptr, fgw, nullptr, HH, HH, nullptr, nullptr);

    // result = fused @ outp_w + outp_b
    gemm3_k<3><<<dim3(4, 64), 128>>>(nullptr, outp_w, outp, DD, HH, outp_b, nullptr);
}

// round 5
// speedup vs baseline: 1.1151x; 1.1151x over previous
#include <cuda_runtime.h>
#include <cuda_bf16.h>
#include <math.h>
#include <stdint.h>

#define NN   8192
#define DD   200
#define BB   4
#define EE   4096
#define DEG  16
#define HH   128
#define EPSf 1e-8f

// ---------------- scratch (device globals; no allocation allowed) ----------------
__device__ float g_out[NN * DD];      // x @ W
__device__ float g_hyper[NN * DD];    // L @ out
__device__ float g_Medge[EE * DD];
__device__ float g_gp[NN * HH];
__device__ float g_fused[NN * HH];
__device__ int   g_dv_cnt[NN];
__device__ int   g_cursor[NN];
__device__ int   g_de_cnt[EE];
__device__ unsigned g_maskbits[EE];
__device__ int   g_offsets[NN];
__device__ int   g_node_edges[EE * DEG];
__device__ float g_alpha_part[256];
__device__ float g_alpha;
__device__ float g_att[BB * HH];
__device__ float g_cvec[BB * HH];

// ---------------- misc small kernels ----------------
__global__ void k_zero() {
    int i = blockIdx.x * blockDim.x + threadIdx.x;
    if (i < NN) { g_dv_cnt[i] = 0; g_cursor[i] = 0; }
}

__global__ void k_alpha_part(const float* __restrict__ x, const float* __restrict__ gw) {
    __shared__ float sm[256];
    int t = threadIdx.x;
    float s = 0.f;
    for (int i = blockIdx.x * 256 + t; i < NN * DD; i += 256 * 256)
        s += x[i] * gw[i % DD];
    sm[t] = s; __syncthreads();
    for (int o = 128; o > 0; o >>= 1) { if (t < o) sm[t] += sm[t + o]; __syncthreads(); }
    if (t == 0) g_alpha_part[blockIdx.x] = sm[0];
}

__global__ void k_alpha_fin(const float* __restrict__ gb) {
    __shared__ float sm[256];
    int t = threadIdx.x;
    sm[t] = g_alpha_part[t]; __syncthreads();
    for (int o = 128; o > 0; o >>= 1) { if (t < o) sm[t] += sm[t + o]; __syncthreads(); }
    if (t == 0) g_alpha = 1.f / (1.f + expf(-(sm[0] / (float)NN + gb[0])));
}

// ---------------- hypergraph sparse stages ----------------
__global__ void k_edge_a(const int* __restrict__ en) {
    int e = blockIdx.x * blockDim.x + threadIdx.x;
    if (e >= EE) return;
    int nd[DEG];
#pragma unroll
    for (int s = 0; s < DEG; s++) nd[s] = en[e * DEG + s];
    unsigned m = 0; int uniq = 0;
#pragma unroll
    for (int s = 0; s < DEG; s++) {
        bool first = true;
        for (int j = 0; j < s; j++) if (nd[j] == nd[s]) { first = false; break; }
        if (first) { m |= (1u << s); uniq++; atomicAdd(&g_dv_cnt[nd[s]], 1); }
    }
    g_maskbits[e] = m;
    g_de_cnt[e] = uniq;
}

__global__ void k_scan() {
    __shared__ int part[256];
    int t = threadIdx.x;
    int base = t * 32;
    int s = 0;
    for (int i = 0; i < 32; i++) s += g_dv_cnt[base + i];
    part[t] = s; __syncthreads();
    for (int off = 1; off < 256; off <<= 1) {
        int v = 0;
        if (t >= off) v = part[t - off];
        __syncthreads();
        part[t] += v;
        __syncthreads();
    }
    int run = (t == 0) ? 0 : part[t - 1];
    for (int i = 0; i < 32; i++) { g_offsets[base + i] = run; run += g_dv_cnt[base + i]; }
}

__global__ void k_fill(const int* __restrict__ en) {
    int e = blockIdx.x * blockDim.x + threadIdx.x;
    if (e >= EE) return;
    unsigned m = g_maskbits[e];
    for (int s = 0; s < DEG; s++) if ((m >> s) & 1u) {
        int n = en[e * DEG + s];
        int p = atomicAdd(&g_cursor[n], 1);
        g_node_edges[g_offsets[n] + p] = e;
    }
}

__global__ void k_sort() {
    int n = blockIdx.x * blockDim.x + threadIdx.x;
    if (n >= NN) return;
    int len = g_dv_cnt[n];
    int* a = &g_node_edges[g_offsets[n]];
    for (int i = 1; i < len; i++) {
        int key = a[i]; int j = i - 1;
        while (j >= 0 && a[j] > key) { a[j + 1] = a[j]; j--; }
        a[j + 1] = key;
    }
}

__global__ void k_edge_b(const int* __restrict__ en) {
    int e = blockIdx.x;
    __shared__ int   sn[DEG];
    __shared__ float sw[DEG];
    int t = threadIdx.x;
    if (t < DEG) {
        int n = en[e * DEG + t];
        sn[t] = n;
        sw[t] = ((g_maskbits[e] >> t) & 1u)
                  ? rsqrtf((float)g_dv_cnt[n] * (1.f / DEG) + EPSf) : 0.f;
    }
    __syncthreads();
    if (t >= DD / 4) return;
    float4 acc = make_float4(0.f, 0.f, 0.f, 0.f);
#pragma unroll
    for (int s = 0; s < DEG; s++) {
        float w = sw[s];
        float4 v = ((const float4*)&g_out[sn[s] * DD])[t];
        acc.x += w * v.x; acc.y += w * v.y; acc.z += w * v.z; acc.w += w * v.w;
    }
    float sc = 1.f / ((float)g_de_cnt[e] * (1.f / DEG) + EPSf) * (1.f / (DEG * DEG));
    ((float4*)&g_Medge[e * DD])[t] =
        make_float4(acc.x * sc, acc.y * sc, acc.z * sc, acc.w * sc);
}

__global__ void k_gather() {
    int n = blockIdx.x;
    int t = threadIdx.x;
    int len  = g_dv_cnt[n];
    int base = g_offsets[n];
    float dvn = rsqrtf((float)len * (1.f / DEG) + EPSf);
    if (t >= DD / 4) return;
    float4 acc = make_float4(0.f, 0.f, 0.f, 0.f);
    for (int i = 0; i < len; i++) {
        int e = g_node_edges[base + i];
        float4 v = ((const float4*)&g_Medge[e * DD])[t];
        acc.x += v.x; acc.y += v.y; acc.z += v.z; acc.w += v.w;
    }
    ((float4*)&g_hyper[n * DD])[t] =
        make_float4(acc.x * dvn, acc.y * dvn, acc.z * dvn, acc.w * dvn);
}

// ---------------- per-batch constants ----------------
__global__ void k_const(const float* __restrict__ text,
                        const float* __restrict__ text_w, const float* __restrict__ text_b,
                        const float* __restrict__ in_w,   const float* __restrict__ in_b,
                        const float* __restrict__ aow,    const float* __restrict__ aob,
                        const float* __restrict__ fgw,    const float* __restrict__ fgb) {
    __shared__ float tp[BB][HH];
    __shared__ float vv[BB][HH];
    __shared__ float at[BB][HH];
    int j = threadIdx.x;  // 128 threads
    for (int b = 0; b < BB; b++) {
        float s = text_b[j];
        for (int k = 0; k < DD; k++) s += text[b * DD + k] * text_w[k * HH + j];
        tp[b][j] = s;
    }
    __syncthreads();
    for (int b = 0; b < BB; b++) {
        float s = in_b[2 * HH + j];
        for (int k = 0; k < HH; k++) s += tp[b][k] * in_w[k * 3 * HH + 2 * HH + j];
        vv[b][j] = s;
    }
    __syncthreads();
    for (int b = 0; b < BB; b++) {
        float s = aob[j];
        for (int k = 0; k < HH; k++) s += vv[b][k] * aow[k * HH + j];
        at[b][j] = s;
        g_att[b * HH + j] = s;
    }
    __syncthreads();
    for (int b = 0; b < BB; b++) {
        float s = fgb[j];
        for (int k = 0; k < HH; k++) s += at[b][k] * fgw[(HH + k) * HH + j];
        g_cvec[b * HH + j] = s;
    }
}

// ---------------- tensor-core GEMM: mma.sync bf16, 3-term split, fp32 accum ----------------
// block: 256 thr = 8 warps (4 M x 2 N); tile 128(M) x 64(N); K-chunk 32
// MODE 0: g_out = x@W ; 1: g_gp = blend@gnn_w + b ; 2: g_fused = gate epi ; 3: Cext = fused@outp_w + b
__device__ __forceinline__ void mma_bf16(float* c, uint32_t a0, uint32_t a1,
                                         uint32_t a2, uint32_t a3,
                                         uint32_t b0, uint32_t b1) {
    asm volatile("mma.sync.aligned.m16n8k16.row.col.f32.bf16.bf16.f32 "
        "{%0,%1,%2,%3}, {%4,%5,%6,%7}, {%8,%9}, {%0,%1,%2,%3};"
        : "+f"(c[0]), "+f"(c[1]), "+f"(c[2]), "+f"(c[3])
        : "r"(a0), "r"(a1), "r"(a2), "r"(a3), "r"(b0), "r"(b1));
}
__device__ __forceinline__ void split2(float v0, float v1, uint32_t& hi, uint32_t& lo) {
    __nv_bfloat16 h0 = __float2bfloat16(v0), h1 = __float2bfloat16(v1);
    float l0 = v0 - __bfloat162float(h0);
    float l1 = v1 - __bfloat162float(h1);
    hi = (uint32_t)__bfloat16_as_ushort(h0) | ((uint32_t)__bfloat16_as_ushort(h1) << 16);
    lo = (uint32_t)__bfloat16_as_ushort(__float2bfloat16(l0))
       | ((uint32_t)__bfloat16_as_ushort(__float2bfloat16(l1)) << 16);
}

#define AS 40   // smem k-stride (bf16 elems): 80B rows -> conflict-free frag loads

template <int MODE>
__global__ void __launch_bounds__(256)
tgemm(const float* __restrict__ Aext, const float* __restrict__ Bsrc,
      float* __restrict__ Cext, const float* __restrict__ bias,
      const float* __restrict__ avec) {
    constexpr int NCOLS = (MODE == 0 || MODE == 3) ? 200 : 128;
    constexpr int K     = (MODE <= 1) ? 200 : 128;
    constexpr int LDA   = (MODE <= 1) ? 200 : 128;
    constexpr int NCH   = (K + 31) / 32;

    __shared__ __nv_bfloat16 Ahs[128][AS], Als[128][AS];
    __shared__ __nv_bfloat16 Bhs[64][AS],  Bls[64][AS];

    const float* A = (MODE == 1) ? (const float*)g_out
                   : (MODE == 2) ? (const float*)g_gp
                   : (MODE == 3) ? (const float*)g_fused : Aext;
    float* C = (MODE == 0) ? (float*)g_out
             : (MODE == 1) ? (float*)g_gp
             : (MODE == 2) ? (float*)g_fused : Cext;

    const int tid = threadIdx.x;
    const int lane = tid & 31;
    const int w = tid >> 5;
    const int wm = w & 3, wn = w >> 2;
    const int g = lane >> 2, tig = lane & 3;
    const int m0 = blockIdx.y * 128, n0 = blockIdx.x * 64;

    float alpha = 0.f, beta = 0.f;
    if (MODE == 1) { alpha = g_alpha; beta = 1.f - alpha; }

    float acc[2][4][4];
#pragma unroll
    for (int mt = 0; mt < 2; mt++)
#pragma unroll
        for (int nt = 0; nt < 4; nt++)
#pragma unroll
            for (int j = 0; j < 4; j++) acc[mt][nt][j] = 0.f;

    const float4 z4 = make_float4(0.f, 0.f, 0.f, 0.f);

    for (int ch = 0; ch < NCH; ch++) {
        const int k0 = ch * 32;
        // ---- A slab: 128 rows x 32 k, 1024 float4, 4/thread ----
#pragma unroll
        for (int i = 0; i < 4; i++) {
            int idx = tid + i * 256;
            int row = idx >> 3, kq = (idx & 7) * 4;
            int gk = k0 + kq;
            float4 v = z4;
            if (gk < K) {
                size_t base = (size_t)(m0 + row) * LDA + gk;
                if (MODE == 1) {
                    float4 o = *(const float4*)&A[base];
                    float4 h = *(const float4*)&g_hyper[base];
                    float4 av = *(const float4*)&avec[gk];
                    v = make_float4(alpha*o.x + beta*h.x + av.x, alpha*o.y + beta*h.y + av.y,
                                    alpha*o.z + beta*h.z + av.z, alpha*o.w + beta*h.w + av.w);
                } else v = *(const float4*)&A[base];
            }
            uint32_t h0, l0, h1, l1;
            split2(v.x, v.y, h0, l0);
            split2(v.z, v.w, h1, l1);
            *(uint32_t*)&Ahs[row][kq]     = h0;
            *(uint32_t*)&Ahs[row][kq + 2] = h1;
            *(uint32_t*)&Als[row][kq]     = l0;
            *(uint32_t*)&Als[row][kq + 2] = l1;
        }
        // ---- B slab: 32 k x 64 n (transpose), 512 float4, 2/thread ----
#pragma unroll
        for (int i = 0; i < 2; i++) {
            int idx = tid + i * 256;
            int kk = idx >> 4, nq = (idx & 15) * 4;
            int gk = k0 + kk, gn = n0 + nq;
            float4 v = z4;
            if (gk < K && gn < NCOLS) v = *(const float4*)&Bsrc[(size_t)gk * NCOLS + gn];
            float e[4] = {v.x, v.y, v.z, v.w};
#pragma unroll
            for (int q = 0; q < 4; q++) {
                __nv_bfloat16 h = __float2bfloat16(e[q]);
                Bhs[nq + q][kk] = h;
                Bls[nq + q][kk] = __float2bfloat16(e[q] - __bfloat162float(h));
            }
        }
        __syncthreads();
        // ---- 2 k-steps of 16 ----
#pragma unroll
        for (int ks = 0; ks < 32; ks += 16) {
            uint32_t ah[2][4], al[2][4];
#pragma unroll
            for (int mt = 0; mt < 2; mt++) {
                int r = wm * 32 + mt * 16 + g;
                ah[mt][0] = *(const uint32_t*)&Ahs[r][ks + tig * 2];
                ah[mt][1] = *(const uint32_t*)&Ahs[r + 8][ks + tig * 2];
                ah[mt][2] = *(const uint32_t*)&Ahs[r][ks + tig * 2 + 8];
                ah[mt][3] = *(const uint32_t*)&Ahs[r + 8][ks + tig * 2 + 8];
                al[mt][0] = *(const uint32_t*)&Als[r][ks + tig * 2];
                al[mt][1] = *(const uint32_t*)&Als[r + 8][ks + tig * 2];
                al[mt][2] = *(const uint32_t*)&Als[r][ks + tig * 2 + 8];
                al[mt][3] = *(const uint32_t*)&Als[r + 8][ks + tig * 2 + 8];
            }
            uint32_t bh[4][2], bl[4][2];
#pragma unroll
            for (int nt = 0; nt < 4; nt++) {
                int n = wn * 32 + nt * 8 + g;
                bh[nt][0] = *(const uint32_t*)&Bhs[n][ks + tig * 2];
                bh[nt][1] = *(const uint32_t*)&Bhs[n][ks + tig * 2 + 8];
                bl[nt][0] = *(const uint32_t*)&Bls[n][ks + tig * 2];
                bl[nt][1] = *(const uint32_t*)&Bls[n][ks + tig * 2 + 8];
            }
#pragma unroll
            for (int mt = 0; mt < 2; mt++)
#pragma unroll
                for (int nt = 0; nt < 4; nt++) {
                    mma_bf16(acc[mt][nt], ah[mt][0], ah[mt][1], ah[mt][2], ah[mt][3],
                             bh[nt][0], bh[nt][1]);
                    mma_bf16(acc[mt][nt], al[mt][0], al[mt][1], al[mt][2], al[mt][3],
                             bh[nt][0], bh[nt][1]);
                    mma_bf16(acc[mt][nt], ah[mt][0], ah[mt][1], ah[mt][2], ah[mt][3],
                             bl[nt][0], bl[nt][1]);
                }
        }
        __syncthreads();
    }

    // ---- epilogue ----
#pragma unroll
    for (int mt = 0; mt < 2; mt++) {
#pragma unroll
        for (int nt = 0; nt < 4; nt++) {
            int row = m0 + wm * 32 + mt * 16 + g;
            int col = n0 + wn * 32 + nt * 8 + tig * 2;
            if (col >= NCOLS) continue;   // NCOLS even, col even -> col+1 also valid
            float* cc = acc[mt][nt];
#pragma unroll
            for (int h = 0; h < 2; h++) {  // h=0: row, c0/c1 ; h=1: row+8, c2/c3
                int r = row + h * 8;
                float v0 = cc[h * 2], v1 = cc[h * 2 + 1];
                if (MODE == 1 || MODE == 3) {
                    v0 += bias[col]; v1 += bias[col + 1];
                } else if (MODE == 2) {
                    int bi = r >> 11;  // Nn = 2048
                    float gp0 = g_gp[(size_t)r * HH + col];
                    float gp1 = g_gp[(size_t)r * HH + col + 1];
                    float gg0 = 1.f / (1.f + expf(-(v0 + g_cvec[bi * HH + col])));
                    float gg1 = 1.f / (1.f + expf(-(v1 + g_cvec[bi * HH + col + 1])));
                    v0 = gg0 * gp0 + (1.f - gg0) * g_att[bi * HH + col];
                    v1 = gg1 * gp1 + (1.f - gg1) * g_att[bi * HH + col + 1];
                }
                *(float2*)&C[(size_t)r * NCOLS + col] = make_float2(v0, v1);
            }
        }
    }
}

// ---------------- launcher ----------------
extern "C" void kernel_launch(void* const* d_in, const int* in_sizes, int n_in,
                              void* d_out, int out_size) {
    const float* x      = (const float*)d_in[0];
    const float* text   = (const float*)d_in[1];
    const float* W      = (const float*)d_in[2];
    const float* bvec   = (const float*)d_in[3];
    const float* gate_w = (const float*)d_in[4];
    const float* gate_b = (const float*)d_in[5];
    const float* gnn_w  = (const float*)d_in[6];
    const float* gnn_b  = (const float*)d_in[7];
    const float* text_w = (const float*)d_in[8];
    const float* text_b = (const float*)d_in[9];
    const float* in_w   = (const float*)d_in[10];
    const float* in_b   = (const float*)d_in[11];
    const float* aow    = (const float*)d_in[12];
    const float* aob    = (const float*)d_in[13];
    const float* fgw    = (const float*)d_in[14];
    const float* fgb    = (const float*)d_in[15];
    const float* outp_w = (const float*)d_in[16];
    const float* outp_b = (const float*)d_in[17];
    const int*   en     = (const int*)d_in[18];
    float* outp = (float*)d_out;

    k_zero<<<32, 256>>>();
    k_alpha_part<<<256, 256>>>(x, gate_w);
    k_alpha_fin<<<1, 256>>>(gate_b);

    // out = x @ W (tensor)
    tgemm<0><<<dim3(4, 64), 256>>>(x, W, nullptr, nullptr, nullptr);

    // hypergraph propagation
    k_edge_a<<<EE / 256, 256>>>(en);
    k_scan<<<1, 256>>>();
    k_fill<<<EE / 256, 256>>>(en);
    k_sort<<<NN / 256, 256>>>();
    k_edge_b<<<EE, 64>>>(en);
    k_gather<<<NN, 64>>>();

    // per-batch attention constants
    k_const<<<1, 128>>>(text, text_w, text_b, in_w, in_b, aow, aob, fgw, fgb);

    // gp = (alpha*out + (1-alpha)*hyper + b) @ gnn_w + gnn_b
    tgemm<1><<<dim3(2, 64), 256>>>(nullptr, gnn_w, nullptr, gnn_b, bvec);

    // fused = sigmoid(gp @ fgate_w0 + c[b]) * gp + (1-g) * att[b]
    tgemm<2><<<dim3(2, 64), 256>>>(nullptr, fgw, nullptr, nullptr, nullptr);

    // result = fused @ outp_w + outp_b
    tgemm<3><<<dim3(4, 64), 256>>>(nullptr, outp_w, outp, outp_b, nullptr);
}

// round 6
// speedup vs baseline: 1.5164x; 1.3599x over previous
#include <cuda_runtime.h>
#include <cuda_bf16.h>
#include <math.h>
#include <stdint.h>

#define NN   8192
#define DD   200
#define BB   4
#define EE   4096
#define DEG  16
#define HH   128
#define EPSf 1e-8f

// ---------------- scratch (device globals; no allocation allowed) ----------------
__device__ float g_out[NN * DD];      // x @ W
__device__ float g_hyper[NN * DD];    // L @ out
__device__ float g_Medge[EE * DD];
__device__ float g_gp[NN * HH];
__device__ float g_fused[NN * HH];
__device__ int   g_dv_cnt[NN];
__device__ int   g_cursor[NN];
__device__ int   g_de_cnt[EE];
__device__ unsigned g_maskbits[EE];
__device__ int   g_offsets[NN];
__device__ int   g_node_edges[EE * DEG];
__device__ float g_alpha_part[256];
__device__ float g_alpha;
__device__ float g_att[BB * HH];
__device__ float g_cvec[BB * HH];

// ---------------- misc small kernels ----------------
__global__ void k_zero() {
    int i = blockIdx.x * blockDim.x + threadIdx.x;
    if (i < NN) { g_dv_cnt[i] = 0; g_cursor[i] = 0; }
}

__global__ void k_alpha_part(const float* __restrict__ x, const float* __restrict__ gw) {
    __shared__ float sm[256];
    int t = threadIdx.x;
    float s = 0.f;
    for (int i = blockIdx.x * 256 + t; i < NN * DD; i += 256 * 256)
        s += x[i] * gw[i % DD];
    sm[t] = s; __syncthreads();
    for (int o = 128; o > 0; o >>= 1) { if (t < o) sm[t] += sm[t + o]; __syncthreads(); }
    if (t == 0) g_alpha_part[blockIdx.x] = sm[0];
}

__global__ void k_alpha_fin(const float* __restrict__ gb) {
    __shared__ float sm[256];
    int t = threadIdx.x;
    sm[t] = g_alpha_part[t]; __syncthreads();
    for (int o = 128; o > 0; o >>= 1) { if (t < o) sm[t] += sm[t + o]; __syncthreads(); }
    if (t == 0) g_alpha = 1.f / (1.f + expf(-(sm[0] / (float)NN + gb[0])));
}

// ---------------- hypergraph sparse stages ----------------
__global__ void k_edge_a(const int* __restrict__ en) {
    int e = blockIdx.x * blockDim.x + threadIdx.x;
    if (e >= EE) return;
    int nd[DEG];
#pragma unroll
    for (int s = 0; s < DEG; s++) nd[s] = en[e * DEG + s];
    unsigned m = 0; int uniq = 0;
#pragma unroll
    for (int s = 0; s < DEG; s++) {
        bool first = true;
        for (int j = 0; j < s; j++) if (nd[j] == nd[s]) { first = false; break; }
        if (first) { m |= (1u << s); uniq++; atomicAdd(&g_dv_cnt[nd[s]], 1); }
    }
    g_maskbits[e] = m;
    g_de_cnt[e] = uniq;
}

__global__ void k_scan() {
    __shared__ int part[256];
    int t = threadIdx.x;
    int base = t * 32;
    int s = 0;
    for (int i = 0; i < 32; i++) s += g_dv_cnt[base + i];
    part[t] = s; __syncthreads();
    for (int off = 1; off < 256; off <<= 1) {
        int v = 0;
        if (t >= off) v = part[t - off];
        __syncthreads();
        part[t] += v;
        __syncthreads();
    }
    int run = (t == 0) ? 0 : part[t - 1];
    for (int i = 0; i < 32; i++) { g_offsets[base + i] = run; run += g_dv_cnt[base + i]; }
}

__global__ void k_fill(const int* __restrict__ en) {
    int e = blockIdx.x * blockDim.x + threadIdx.x;
    if (e >= EE) return;
    unsigned m = g_maskbits[e];
    for (int s = 0; s < DEG; s++) if ((m >> s) & 1u) {
        int n = en[e * DEG + s];
        int p = atomicAdd(&g_cursor[n], 1);
        g_node_edges[g_offsets[n] + p] = e;
    }
}

__global__ void k_sort() {
    int n = blockIdx.x * blockDim.x + threadIdx.x;
    if (n >= NN) return;
    int len = g_dv_cnt[n];
    int* a = &g_node_edges[g_offsets[n]];
    for (int i = 1; i < len; i++) {
        int key = a[i]; int j = i - 1;
        while (j >= 0 && a[j] > key) { a[j + 1] = a[j]; j--; }
        a[j + 1] = key;
    }
}

__global__ void k_edge_b(const int* __restrict__ en) {
    int e = blockIdx.x;
    __shared__ int   sn[DEG];
    __shared__ float sw[DEG];
    int t = threadIdx.x;
    if (t < DEG) {
        int n = en[e * DEG + t];
        sn[t] = n;
        sw[t] = ((g_maskbits[e] >> t) & 1u)
                  ? rsqrtf((float)g_dv_cnt[n] * (1.f / DEG) + EPSf) : 0.f;
    }
    __syncthreads();
    if (t >= DD / 4) return;
    float4 acc = make_float4(0.f, 0.f, 0.f, 0.f);
#pragma unroll
    for (int s = 0; s < DEG; s++) {
        float w = sw[s];
        float4 v = ((const float4*)&g_out[sn[s] * DD])[t];
        acc.x += w * v.x; acc.y += w * v.y; acc.z += w * v.z; acc.w += w * v.w;
    }
    float sc = 1.f / ((float)g_de_cnt[e] * (1.f / DEG) + EPSf) * (1.f / (DEG * DEG));
    ((float4*)&g_Medge[e * DD])[t] =
        make_float4(acc.x * sc, acc.y * sc, acc.z * sc, acc.w * sc);
}

__global__ void k_gather() {
    int n = blockIdx.x;
    int t = threadIdx.x;
    int len  = g_dv_cnt[n];
    int base = g_offsets[n];
    float dvn = rsqrtf((float)len * (1.f / DEG) + EPSf);
    if (t >= DD / 4) return;
    float4 acc = make_float4(0.f, 0.f, 0.f, 0.f);
    for (int i = 0; i < len; i++) {
        int e = g_node_edges[base + i];
        float4 v = ((const float4*)&g_Medge[e * DD])[t];
        acc.x += v.x; acc.y += v.y; acc.z += v.z; acc.w += v.w;
    }
    ((float4*)&g_hyper[n * DD])[t] =
        make_float4(acc.x * dvn, acc.y * dvn, acc.z * dvn, acc.w * dvn);
}

// ---------------- per-batch constants (one block per batch) ----------------
__global__ void k_const(const float* __restrict__ text,
                        const float* __restrict__ text_w, const float* __restrict__ text_b,
                        const float* __restrict__ in_w,   const float* __restrict__ in_b,
                        const float* __restrict__ aow,    const float* __restrict__ aob,
                        const float* __restrict__ fgw,    const float* __restrict__ fgb) {
    __shared__ float tp[HH];
    __shared__ float vv[HH];
    __shared__ float at[HH];
    int b = blockIdx.x;
    int j = threadIdx.x;  // 128 threads
    {
        float s = text_b[j];
        for (int k = 0; k < DD; k++) s += text[b * DD + k] * text_w[k * HH + j];
        tp[j] = s;
    }
    __syncthreads();
    {
        float s = in_b[2 * HH + j];
        for (int k = 0; k < HH; k++) s += tp[k] * in_w[k * 3 * HH + 2 * HH + j];
        vv[j] = s;
    }
    __syncthreads();
    {
        float s = aob[j];
        for (int k = 0; k < HH; k++) s += vv[k] * aow[k * HH + j];
        at[j] = s;
        g_att[b * HH + j] = s;
    }
    __syncthreads();
    {
        float s = fgb[j];
        for (int k = 0; k < HH; k++) s += at[k] * fgw[(HH + k) * HH + j];
        g_cvec[b * HH + j] = s;
    }
}

// ---------------- tensor-core GEMM v2: pipelined, packed hi/lo smem ----------------
// block 256 thr = 8 warps (4 M x 2 N); tile 128(M) x 64(N); K-chunk 32
// smem u32 layout: row-major, stride 40 u32; u32 offset k holds hi-pair(k,k+1) for
// even k, offset k+1 holds lo-pair. Frag loads are conflict-free LDS.64.
__device__ __forceinline__ void mma_bf16(float* c, uint32_t a0, uint32_t a1,
                                         uint32_t a2, uint32_t a3,
                                         uint32_t b0, uint32_t b1) {
    asm volatile("mma.sync.aligned.m16n8k16.row.col.f32.bf16.bf16.f32 "
        "{%0,%1,%2,%3}, {%4,%5,%6,%7}, {%8,%9}, {%0,%1,%2,%3};"
        : "+f"(c[0]), "+f"(c[1]), "+f"(c[2]), "+f"(c[3])
        : "r"(a0), "r"(a1), "r"(a2), "r"(a3), "r"(b0), "r"(b1));
}
__device__ __forceinline__ void split2(float v0, float v1, uint32_t& hi, uint32_t& lo) {
    __nv_bfloat16 h0 = __float2bfloat16(v0), h1 = __float2bfloat16(v1);
    float l0 = v0 - __bfloat162float(h0);
    float l1 = v1 - __bfloat162float(h1);
    hi = (uint32_t)__bfloat16_as_ushort(h0) | ((uint32_t)__bfloat16_as_ushort(h1) << 16);
    lo = (uint32_t)__bfloat16_as_ushort(__float2bfloat16(l0))
       | ((uint32_t)__bfloat16_as_ushort(__float2bfloat16(l1)) << 16);
}

#define PST 40   // u32 row stride

template <int MODE>
__global__ void __launch_bounds__(256)
tgemm(const float* __restrict__ Aext, const float* __restrict__ Bsrc,
      float* __restrict__ Cext, const float* __restrict__ bias,
      const float* __restrict__ avec) {
    constexpr int NCOLS = (MODE == 0 || MODE == 3) ? 200 : 128;
    constexpr int K     = (MODE <= 1) ? 200 : 128;
    constexpr int LDA   = (MODE <= 1) ? 200 : 128;
    constexpr int NCH   = (K + 31) / 32;

    __shared__ uint32_t Ap[128][PST];   // 20.5 KB
    __shared__ uint32_t Bp[64][PST];    // 10.2 KB

    const float* A = (MODE == 1) ? (const float*)g_out
                   : (MODE == 2) ? (const float*)g_gp
                   : (MODE == 3) ? (const float*)g_fused : Aext;
    float* C = (MODE == 0) ? (float*)g_out
             : (MODE == 1) ? (float*)g_gp
             : (MODE == 2) ? (float*)g_fused : Cext;

    const int tid = threadIdx.x;
    const int lane = tid & 31;
    const int w = tid >> 5;
    const int wm = w & 3, wn = w >> 2;
    const int g = lane >> 2, tig = lane & 3;
    const int m0 = blockIdx.y * 128, n0 = blockIdx.x * 64;

    float alpha = 0.f, beta = 0.f;
    if (MODE == 1) { alpha = g_alpha; beta = 1.f - alpha; }

    // A loader mapping: idx = tid + i*256; row = idx>>3, kq = (idx&7)*4
    const int a_row = tid >> 3, a_kq = (tid & 7) * 4;
    // B loader mapping: kpair m = tid&15 (k = 2m, 2m+1), nq = (tid>>4)*4
    const int b_m = tid & 15, b_nq = (tid >> 4) * 4;

    float acc[2][4][4];
#pragma unroll
    for (int mt = 0; mt < 2; mt++)
#pragma unroll
        for (int nt = 0; nt < 4; nt++)
#pragma unroll
            for (int j = 0; j < 4; j++) acc[mt][nt][j] = 0.f;

    const float4 z4 = make_float4(0.f, 0.f, 0.f, 0.f);
    float4 ar[4];        // A raw prefetch
    float4 br0, br1;     // B raw prefetch (k = 2m, 2m+1)

    auto load_raw = [&](int k0) {
#pragma unroll
        for (int i = 0; i < 4; i++) {
            int row = a_row + i * 32;
            int gk = k0 + a_kq;
            float4 v = z4;
            if (gk < K) {
                size_t base = (size_t)(m0 + row) * LDA + gk;
                if (MODE == 1) {
                    float4 o = *(const float4*)&A[base];
                    float4 h = *(const float4*)&g_hyper[base];
                    float4 av = *(const float4*)&avec[gk];
                    v = make_float4(alpha*o.x + beta*h.x + av.x, alpha*o.y + beta*h.y + av.y,
                                    alpha*o.z + beta*h.z + av.z, alpha*o.w + beta*h.w + av.w);
                } else v = *(const float4*)&A[base];
            }
            ar[i] = v;
        }
        int gk0 = k0 + 2 * b_m, gk1 = gk0 + 1, gn = n0 + b_nq;
        br0 = (gk0 < K && gn < NCOLS) ? *(const float4*)&Bsrc[(size_t)gk0 * NCOLS + gn] : z4;
        br1 = (gk1 < K && gn < NCOLS) ? *(const float4*)&Bsrc[(size_t)gk1 * NCOLS + gn] : z4;
    };
    auto store_smem = [&]() {
#pragma unroll
        for (int i = 0; i < 4; i++) {
            int row = a_row + i * 32;
            uint32_t h0, l0, h1, l1;
            split2(ar[i].x, ar[i].y, h0, l0);
            split2(ar[i].z, ar[i].w, h1, l1);
            Ap[row][a_kq + 0] = h0;
            Ap[row][a_kq + 1] = l0;
            Ap[row][a_kq + 2] = h1;
            Ap[row][a_kq + 3] = l1;
        }
        float b0e[4] = {br0.x, br0.y, br0.z, br0.w};
        float b1e[4] = {br1.x, br1.y, br1.z, br1.w};
#pragma unroll
        for (int q = 0; q < 4; q++) {
            uint32_t hi, lo;
            split2(b0e[q], b1e[q], hi, lo);
            Bp[b_nq + q][2 * b_m]     = hi;
            Bp[b_nq + q][2 * b_m + 1] = lo;
        }
    };

    load_raw(0);
    store_smem();
    __syncthreads();

    for (int ch = 0; ch < NCH; ch++) {
        if (ch + 1 < NCH) load_raw((ch + 1) * 32);   // LDG in flight during MMAs
#pragma unroll
        for (int ks = 0; ks < 32; ks += 16) {
            uint32_t ah[2][4], al[2][4];
#pragma unroll
            for (int mt = 0; mt < 2; mt++) {
                int r = wm * 32 + mt * 16 + g;
                uint2 p0 = *(const uint2*)&Ap[r][ks + tig * 2];
                uint2 p1 = *(const uint2*)&Ap[r + 8][ks + tig * 2];
                uint2 p2 = *(const uint2*)&Ap[r][ks + tig * 2 + 8];
                uint2 p3 = *(const uint2*)&Ap[r + 8][ks + tig * 2 + 8];
                ah[mt][0] = p0.x; al[mt][0] = p0.y;
                ah[mt][1] = p1.x; al[mt][1] = p1.y;
                ah[mt][2] = p2.x; al[mt][2] = p2.y;
                ah[mt][3] = p3.x; al[mt][3] = p3.y;
            }
            uint32_t bh[4][2], bl[4][2];
#pragma unroll
            for (int nt = 0; nt < 4; nt++) {
                int n = wn * 32 + nt * 8 + g;
                uint2 q0 = *(const uint2*)&Bp[n][ks + tig * 2];
                uint2 q1 = *(const uint2*)&Bp[n][ks + tig * 2 + 8];
                bh[nt][0] = q0.x; bl[nt][0] = q0.y;
                bh[nt][1] = q1.x; bl[nt][1] = q1.y;
            }
#pragma unroll
            for (int mt = 0; mt < 2; mt++)
#pragma unroll
                for (int nt = 0; nt < 4; nt++) {
                    mma_bf16(acc[mt][nt], ah[mt][0], ah[mt][1], ah[mt][2], ah[mt][3],
                             bh[nt][0], bh[nt][1]);
                    mma_bf16(acc[mt][nt], al[mt][0], al[mt][1], al[mt][2], al[mt][3],
                             bh[nt][0], bh[nt][1]);
                    mma_bf16(acc[mt][nt], ah[mt][0], ah[mt][1], ah[mt][2], ah[mt][3],
                             bl[nt][0], bl[nt][1]);
                }
        }
        __syncthreads();
        if (ch + 1 < NCH) {
            store_smem();
            __syncthreads();
        }
    }

    // ---- epilogue ----
#pragma unroll
    for (int mt = 0; mt < 2; mt++) {
#pragma unroll
        for (int nt = 0; nt < 4; nt++) {
            int row = m0 + wm * 32 + mt * 16 + g;
            int col = n0 + wn * 32 + nt * 8 + tig * 2;
            if (col >= NCOLS) continue;   // NCOLS even -> col+1 also valid
            float* cc = acc[mt][nt];
#pragma unroll
            for (int h = 0; h < 2; h++) {
                int r = row + h * 8;
                float v0 = cc[h * 2], v1 = cc[h * 2 + 1];
                if (MODE == 1 || MODE == 3) {
                    v0 += bias[col]; v1 += bias[col + 1];
                } else if (MODE == 2) {
                    int bi = r >> 11;  // Nn = 2048
                    float gp0 = g_gp[(size_t)r * HH + col];
                    float gp1 = g_gp[(size_t)r * HH + col + 1];
                    float gg0 = 1.f / (1.f + expf(-(v0 + g_cvec[bi * HH + col])));
                    float gg1 = 1.f / (1.f + expf(-(v1 + g_cvec[bi * HH + col + 1])));
                    v0 = gg0 * gp0 + (1.f - gg0) * g_att[bi * HH + col];
                    v1 = gg1 * gp1 + (1.f - gg1) * g_att[bi * HH + col + 1];
                }
                *(float2*)&C[(size_t)r * NCOLS + col] = make_float2(v0, v1);
            }
        }
    }
}

// ---------------- launcher ----------------
extern "C" void kernel_launch(void* const* d_in, const int* in_sizes, int n_in,
                              void* d_out, int out_size) {
    const float* x      = (const float*)d_in[0];
    const float* text   = (const float*)d_in[1];
    const float* W      = (const float*)d_in[2];
    const float* bvec   = (const float*)d_in[3];
    const float* gate_w = (const float*)d_in[4];
    const float* gate_b = (const float*)d_in[5];
    const float* gnn_w  = (const float*)d_in[6];
    const float* gnn_b  = (const float*)d_in[7];
    const float* text_w = (const float*)d_in[8];
    const float* text_b = (const float*)d_in[9];
    const float* in_w   = (const float*)d_in[10];
    const float* in_b   = (const float*)d_in[11];
    const float* aow    = (const float*)d_in[12];
    const float* aob    = (const float*)d_in[13];
    const float* fgw    = (const float*)d_in[14];
    const float* fgb    = (const float*)d_in[15];
    const float* outp_w = (const float*)d_in[16];
    const float* outp_b = (const float*)d_in[17];
    const int*   en     = (const int*)d_in[18];
    float* outp = (float*)d_out;

    k_zero<<<32, 256>>>();
    k_alpha_part<<<256, 256>>>(x, gate_w);
    k_alpha_fin<<<1, 256>>>(gate_b);

    // out = x @ W (tensor)
    tgemm<0><<<dim3(4, 64), 256>>>(x, W, nullptr, nullptr, nullptr);

    // hypergraph propagation
    k_edge_a<<<EE / 256, 256>>>(en);
    k_scan<<<1, 256>>>();
    k_fill<<<EE / 256, 256>>>(en);
    k_sort<<<NN / 256, 256>>>();
    k_edge_b<<<EE, 64>>>(en);
    k_gather<<<NN, 64>>>();

    // per-batch attention constants
    k_const<<<BB, 128>>>(text, text_w, text_b, in_w, in_b, aow, aob, fgw, fgb);

    // gp = (alpha*out + (1-alpha)*hyper + b) @ gnn_w + gnn_b
    tgemm<1><<<dim3(2, 64), 256>>>(nullptr, gnn_w, nullptr, gnn_b, bvec);

    // fused = sigmoid(gp @ fgate_w0 + c[b]) * gp + (1-g) * att[b]
    tgemm<2><<<dim3(2, 64), 256>>>(nullptr, fgw, nullptr, nullptr, nullptr);

    // result = fused @ outp_w + outp_b
    tgemm<3><<<dim3(4, 64), 256>>>(nullptr, outp_w, outp, outp_b, nullptr);
}

// round 7
// speedup vs baseline: 1.7357x; 1.1446x over previous
#include <cuda_runtime.h>
#include <cuda_bf16.h>
#include <math.h>
#include <stdint.h>

#define NN   8192
#define DD   200
#define BB   4
#define EE   4096
#define DEG  16
#define HH   128
#define EPSf 1e-8f

// ---------------- scratch (device globals; no allocation allowed) ----------------
__device__ float g_z[NN * DD];        // alpha*x + (1-alpha)*L*x
__device__ float g_Medge[EE * DD];
__device__ float g_gp[NN * HH];
__device__ float g_fused[NN * HH];
__device__ float g_Wg[DD * HH];       // W @ gnn_w
__device__ float g_bg[HH];            // b @ gnn_w + gnn_b
__device__ int   g_dv_cnt[NN];
__device__ int   g_cursor[NN];
__device__ int   g_de_cnt[EE];
__device__ unsigned g_maskbits[EE];
__device__ int   g_offsets[NN];
__device__ int   g_node_edges[EE * DEG];
__device__ float g_alpha_part[256];
__device__ float g_alpha;
__device__ float g_att[BB * HH];
__device__ float g_cvec[BB * HH];

// ---------------- misc small kernels ----------------
__global__ void k_zero() {
    int i = blockIdx.x * blockDim.x + threadIdx.x;
    if (i < NN) { g_dv_cnt[i] = 0; g_cursor[i] = 0; }
}

__global__ void k_alpha_part(const float* __restrict__ x, const float* __restrict__ gw) {
    __shared__ float sm[256];
    int t = threadIdx.x;
    float s = 0.f;
    for (int i = blockIdx.x * 256 + t; i < NN * DD; i += 256 * 256)
        s += x[i] * gw[i % DD];
    sm[t] = s; __syncthreads();
    for (int o = 128; o > 0; o >>= 1) { if (t < o) sm[t] += sm[t + o]; __syncthreads(); }
    if (t == 0) g_alpha_part[blockIdx.x] = sm[0];
}

__global__ void k_alpha_fin(const float* __restrict__ gb) {
    __shared__ float sm[256];
    int t = threadIdx.x;
    sm[t] = g_alpha_part[t]; __syncthreads();
    for (int o = 128; o > 0; o >>= 1) { if (t < o) sm[t] += sm[t + o]; __syncthreads(); }
    if (t == 0) g_alpha = 1.f / (1.f + expf(-(sm[0] / (float)NN + gb[0])));
}

// Wg = W @ gnn_w (200 blocks), bg = b @ gnn_w + gnn_b (block 200)
__global__ void k_prec(const float* __restrict__ W, const float* __restrict__ gnn_w,
                       const float* __restrict__ gnn_b, const float* __restrict__ bvec) {
    __shared__ float rowv[DD];
    int r = blockIdx.x, j = threadIdx.x;  // 128 threads
    const float* src = (r < DD) ? &W[(size_t)r * DD] : bvec;
    for (int i = j; i < DD; i += 128) rowv[i] = src[i];
    __syncthreads();
    float s = 0.f;
    for (int k = 0; k < DD; k++) s += rowv[k] * gnn_w[k * HH + j];
    if (r < DD) g_Wg[r * HH + j] = s;
    else        g_bg[j] = s + gnn_b[j];
}

// ---------------- hypergraph sparse stages (operate on x directly) ----------------
__global__ void k_edge_a(const int* __restrict__ en) {
    int e = blockIdx.x * blockDim.x + threadIdx.x;
    if (e >= EE) return;
    int nd[DEG];
#pragma unroll
    for (int s = 0; s < DEG; s++) nd[s] = en[e * DEG + s];
    unsigned m = 0; int uniq = 0;
#pragma unroll
    for (int s = 0; s < DEG; s++) {
        bool first = true;
        for (int j = 0; j < s; j++) if (nd[j] == nd[s]) { first = false; break; }
        if (first) { m |= (1u << s); uniq++; atomicAdd(&g_dv_cnt[nd[s]], 1); }
    }
    g_maskbits[e] = m;
    g_de_cnt[e] = uniq;
}

__global__ void k_scan() {
    __shared__ int part[256];
    int t = threadIdx.x;
    int base = t * 32;
    int s = 0;
    for (int i = 0; i < 32; i++) s += g_dv_cnt[base + i];
    part[t] = s; __syncthreads();
    for (int off = 1; off < 256; off <<= 1) {
        int v = 0;
        if (t >= off) v = part[t - off];
        __syncthreads();
        part[t] += v;
        __syncthreads();
    }
    int run = (t == 0) ? 0 : part[t - 1];
    for (int i = 0; i < 32; i++) { g_offsets[base + i] = run; run += g_dv_cnt[base + i]; }
}

__global__ void k_fill(const int* __restrict__ en) {
    int e = blockIdx.x * blockDim.x + threadIdx.x;
    if (e >= EE) return;
    unsigned m = g_maskbits[e];
    for (int s = 0; s < DEG; s++) if ((m >> s) & 1u) {
        int n = en[e * DEG + s];
        int p = atomicAdd(&g_cursor[n], 1);
        g_node_edges[g_offsets[n] + p] = e;
    }
}

__global__ void k_sort() {
    int n = blockIdx.x * blockDim.x + threadIdx.x;
    if (n >= NN) return;
    int len = g_dv_cnt[n];
    int* a = &g_node_edges[g_offsets[n]];
    for (int i = 1; i < len; i++) {
        int key = a[i]; int j = i - 1;
        while (j >= 0 && a[j] > key) { a[j + 1] = a[j]; j--; }
        a[j + 1] = key;
    }
}

__global__ void k_edge_b(const int* __restrict__ en, const float* __restrict__ x) {
    int e = blockIdx.x;
    __shared__ int   sn[DEG];
    __shared__ float sw[DEG];
    int t = threadIdx.x;
    if (t < DEG) {
        int n = en[e * DEG + t];
        sn[t] = n;
        sw[t] = ((g_maskbits[e] >> t) & 1u)
                  ? rsqrtf((float)g_dv_cnt[n] * (1.f / DEG) + EPSf) : 0.f;
    }
    __syncthreads();
    if (t >= DD / 4) return;
    float4 acc = make_float4(0.f, 0.f, 0.f, 0.f);
#pragma unroll
    for (int s = 0; s < DEG; s++) {
        float w = sw[s];
        float4 v = ((const float4*)&x[(size_t)sn[s] * DD])[t];
        acc.x += w * v.x; acc.y += w * v.y; acc.z += w * v.z; acc.w += w * v.w;
    }
    float sc = 1.f / ((float)g_de_cnt[e] * (1.f / DEG) + EPSf) * (1.f / (DEG * DEG));
    ((float4*)&g_Medge[e * DD])[t] =
        make_float4(acc.x * sc, acc.y * sc, acc.z * sc, acc.w * sc);
}

// z = alpha*x + (1-alpha) * dv * sum_e M_edge
__global__ void k_gather(const float* __restrict__ x) {
    int n = blockIdx.x;
    int t = threadIdx.x;
    int len  = g_dv_cnt[n];
    int base = g_offsets[n];
    float dvn = rsqrtf((float)len * (1.f / DEG) + EPSf);
    if (t >= DD / 4) return;
    float alpha = g_alpha, beta = 1.f - alpha;
    float4 acc = make_float4(0.f, 0.f, 0.f, 0.f);
    for (int i = 0; i < len; i++) {
        int e = g_node_edges[base + i];
        float4 v = ((const float4*)&g_Medge[e * DD])[t];
        acc.x += v.x; acc.y += v.y; acc.z += v.z; acc.w += v.w;
    }
    float4 xv = ((const float4*)&x[(size_t)n * DD])[t];
    ((float4*)&g_z[(size_t)n * DD])[t] =
        make_float4(alpha * xv.x + beta * dvn * acc.x,
                    alpha * xv.y + beta * dvn * acc.y,
                    alpha * xv.z + beta * dvn * acc.z,
                    alpha * xv.w + beta * dvn * acc.w);
}

// ---------------- per-batch constants (one block per batch) ----------------
__global__ void k_const(const float* __restrict__ text,
                        const float* __restrict__ text_w, const float* __restrict__ text_b,
                        const float* __restrict__ in_w,   const float* __restrict__ in_b,
                        const float* __restrict__ aow,    const float* __restrict__ aob,
                        const float* __restrict__ fgw,    const float* __restrict__ fgb) {
    __shared__ float tp[HH];
    __shared__ float vv[HH];
    __shared__ float at[HH];
    int b = blockIdx.x;
    int j = threadIdx.x;  // 128 threads
    {
        float s = text_b[j];
        for (int k = 0; k < DD; k++) s += text[b * DD + k] * text_w[k * HH + j];
        tp[j] = s;
    }
    __syncthreads();
    {
        float s = in_b[2 * HH + j];
        for (int k = 0; k < HH; k++) s += tp[k] * in_w[k * 3 * HH + 2 * HH + j];
        vv[j] = s;
    }
    __syncthreads();
    {
        float s = aob[j];
        for (int k = 0; k < HH; k++) s += vv[k] * aow[k * HH + j];
        at[j] = s;
        g_att[b * HH + j] = s;
    }
    __syncthreads();
    {
        float s = fgb[j];
        for (int k = 0; k < HH; k++) s += at[k] * fgw[(HH + k) * HH + j];
        g_cvec[b * HH + j] = s;
    }
}

// ---------------- tensor-core GEMM v3: double-buffered, packed hi/lo smem ----------------
// block 256 thr = 8 warps (4 M x 2 N); tile 128(M) x 64(N); K-chunk 32
// MODE 1: g_gp = g_z @ g_Wg + g_bg ; 2: g_fused = gate epi of g_gp @ fgw0 ; 3: Cext = g_fused @ outp_w + bias
__device__ __forceinline__ void mma_bf16(float* c, uint32_t a0, uint32_t a1,
                                         uint32_t a2, uint32_t a3,
                                         uint32_t b0, uint32_t b1) {
    asm volatile("mma.sync.aligned.m16n8k16.row.col.f32.bf16.bf16.f32 "
        "{%0,%1,%2,%3}, {%4,%5,%6,%7}, {%8,%9}, {%0,%1,%2,%3};"
        : "+f"(c[0]), "+f"(c[1]), "+f"(c[2]), "+f"(c[3])
        : "r"(a0), "r"(a1), "r"(a2), "r"(a3), "r"(b0), "r"(b1));
}
__device__ __forceinline__ void split2(float v0, float v1, uint32_t& hi, uint32_t& lo) {
    __nv_bfloat16 h0 = __float2bfloat16(v0), h1 = __float2bfloat16(v1);
    float l0 = v0 - __bfloat162float(h0);
    float l1 = v1 - __bfloat162float(h1);
    hi = (uint32_t)__bfloat16_as_ushort(h0) | ((uint32_t)__bfloat16_as_ushort(h1) << 16);
    lo = (uint32_t)__bfloat16_as_ushort(__float2bfloat16(l0))
       | ((uint32_t)__bfloat16_as_ushort(__float2bfloat16(l1)) << 16);
}

#define PST 40                 // u32 row stride
#define STG2 (192 * PST)       // u32 per stage (128 A rows + 64 B rows)
#define SMEM_BYTES (2 * STG2 * 4)

template <int MODE>
__global__ void __launch_bounds__(256)
tgemm(const float* __restrict__ Bext, float* __restrict__ Cext,
      const float* __restrict__ bias) {
    constexpr int NCOLS = (MODE == 3) ? 200 : 128;
    constexpr int K     = (MODE == 1) ? 200 : 128;
    constexpr int LDA   = (MODE == 1) ? 200 : 128;
    constexpr int NCH   = (K + 31) / 32;

    extern __shared__ uint32_t sm[];

    const float* A = (MODE == 1) ? (const float*)g_z
                   : (MODE == 2) ? (const float*)g_gp : (const float*)g_fused;
    const float* Bsrc = (MODE == 1) ? (const float*)g_Wg : Bext;
    float* C = (MODE == 1) ? (float*)g_gp
             : (MODE == 2) ? (float*)g_fused : Cext;

    const int tid = threadIdx.x;
    const int lane = tid & 31;
    const int w = tid >> 5;
    const int wm = w & 3, wn = w >> 2;
    const int g = lane >> 2, tig = lane & 3;
    const int m0 = blockIdx.y * 128, n0 = blockIdx.x * 64;

    // A loader mapping: row = tid>>3 (+i*32), kq = (tid&7)*4
    const int a_row = tid >> 3, a_kq = (tid & 7) * 4;
    // B loader mapping: kpair m = tid&15 (k = 2m, 2m+1), nq = (tid>>4)*4
    const int b_m = tid & 15, b_nq = (tid >> 4) * 4;

    float acc[2][4][4];
#pragma unroll
    for (int mt = 0; mt < 2; mt++)
#pragma unroll
        for (int nt = 0; nt < 4; nt++)
#pragma unroll
            for (int j = 0; j < 4; j++) acc[mt][nt][j] = 0.f;

    const float4 z4 = make_float4(0.f, 0.f, 0.f, 0.f);
    float4 ar[4];
    float4 br0, br1;

    auto load_raw = [&](int k0) {
#pragma unroll
        for (int i = 0; i < 4; i++) {
            int row = a_row + i * 32;
            int gk = k0 + a_kq;
            ar[i] = (gk < K) ? *(const float4*)&A[(size_t)(m0 + row) * LDA + gk] : z4;
        }
        int gk0 = k0 + 2 * b_m, gk1 = gk0 + 1, gn = n0 + b_nq;
        br0 = (gk0 < K && gn < NCOLS) ? *(const float4*)&Bsrc[(size_t)gk0 * NCOLS + gn] : z4;
        br1 = (gk1 < K && gn < NCOLS) ? *(const float4*)&Bsrc[(size_t)gk1 * NCOLS + gn] : z4;
    };
    auto store_smem = [&](int buf) {
        uint32_t* Ap = sm + buf * STG2;
        uint32_t* Bp = Ap + 128 * PST;
#pragma unroll
        for (int i = 0; i < 4; i++) {
            int row = a_row + i * 32;
            uint32_t h0, l0, h1, l1;
            split2(ar[i].x, ar[i].y, h0, l0);
            split2(ar[i].z, ar[i].w, h1, l1);
            uint32_t* p = Ap + row * PST + a_kq;
            p[0] = h0; p[1] = l0; p[2] = h1; p[3] = l1;
        }
        float b0e[4] = {br0.x, br0.y, br0.z, br0.w};
        float b1e[4] = {br1.x, br1.y, br1.z, br1.w};
#pragma unroll
        for (int q = 0; q < 4; q++) {
            uint32_t hi, lo;
            split2(b0e[q], b1e[q], hi, lo);
            uint32_t* p = Bp + (b_nq + q) * PST + 2 * b_m;
            p[0] = hi; p[1] = lo;
        }
    };

    load_raw(0);
    store_smem(0);
    __syncthreads();

    for (int ch = 0; ch < NCH; ch++) {
        const int buf = ch & 1;
        const uint32_t* Ap = sm + buf * STG2;
        const uint32_t* Bp = Ap + 128 * PST;
        if (ch + 1 < NCH) load_raw((ch + 1) * 32);
#pragma unroll
        for (int ks = 0; ks < 32; ks += 16) {
            uint32_t ah[2][4], al[2][4];
#pragma unroll
            for (int mt = 0; mt < 2; mt++) {
                int r = wm * 32 + mt * 16 + g;
                uint2 p0 = *(const uint2*)(Ap + r * PST + ks + tig * 2);
                uint2 p1 = *(const uint2*)(Ap + (r + 8) * PST + ks + tig * 2);
                uint2 p2 = *(const uint2*)(Ap + r * PST + ks + tig * 2 + 8);
                uint2 p3 = *(const uint2*)(Ap + (r + 8) * PST + ks + tig * 2 + 8);
                ah[mt][0] = p0.x; al[mt][0] = p0.y;
                ah[mt][1] = p1.x; al[mt][1] = p1.y;
                ah[mt][2] = p2.x; al[mt][2] = p2.y;
                ah[mt][3] = p3.x; al[mt][3] = p3.y;
            }
            uint32_t bh[4][2], bl[4][2];
#pragma unroll
            for (int nt = 0; nt < 4; nt++) {
                int n = wn * 32 + nt * 8 + g;
                uint2 q0 = *(const uint2*)(Bp + n * PST + ks + tig * 2);
                uint2 q1 = *(const uint2*)(Bp + n * PST + ks + tig * 2 + 8);
                bh[nt][0] = q0.x; bl[nt][0] = q0.y;
                bh[nt][1] = q1.x; bl[nt][1] = q1.y;
            }
#pragma unroll
            for (int mt = 0; mt < 2; mt++)
#pragma unroll
                for (int nt = 0; nt < 4; nt++) {
                    mma_bf16(acc[mt][nt], ah[mt][0], ah[mt][1], ah[mt][2], ah[mt][3],
                             bh[nt][0], bh[nt][1]);
                    mma_bf16(acc[mt][nt], al[mt][0], al[mt][1], al[mt][2], al[mt][3],
                             bh[nt][0], bh[nt][1]);
                    mma_bf16(acc[mt][nt], ah[mt][0], ah[mt][1], ah[mt][2], ah[mt][3],
                             bl[nt][0], bl[nt][1]);
                }
        }
        if (ch + 1 < NCH) store_smem(buf ^ 1);
        __syncthreads();
    }

    // ---- epilogue ----
#pragma unroll
    for (int mt = 0; mt < 2; mt++) {
#pragma unroll
        for (int nt = 0; nt < 4; nt++) {
            int row = m0 + wm * 32 + mt * 16 + g;
            int col = n0 + wn * 32 + nt * 8 + tig * 2;
            if (col >= NCOLS) continue;   // NCOLS even -> col+1 also valid
            float* cc = acc[mt][nt];
#pragma unroll
            for (int h = 0; h < 2; h++) {
                int r = row + h * 8;
                float v0 = cc[h * 2], v1 = cc[h * 2 + 1];
                if (MODE == 1) {
                    v0 += g_bg[col]; v1 += g_bg[col + 1];
                } else if (MODE == 3) {
                    v0 += bias[col]; v1 += bias[col + 1];
                } else {  // MODE 2
                    int bi = r >> 11;  // Nn = 2048
                    float gp0 = g_gp[(size_t)r * HH + col];
                    float gp1 = g_gp[(size_t)r * HH + col + 1];
                    float gg0 = 1.f / (1.f + expf(-(v0 + g_cvec[bi * HH + col])));
                    float gg1 = 1.f / (1.f + expf(-(v1 + g_cvec[bi * HH + col + 1])));
                    v0 = gg0 * gp0 + (1.f - gg0) * g_att[bi * HH + col];
                    v1 = gg1 * gp1 + (1.f - gg1) * g_att[bi * HH + col + 1];
                }
                *(float2*)&C[(size_t)r * NCOLS + col] = make_float2(v0, v1);
            }
        }
    }
}

// ---------------- launcher ----------------
extern "C" void kernel_launch(void* const* d_in, const int* in_sizes, int n_in,
                              void* d_out, int out_size) {
    const float* x      = (const float*)d_in[0];
    const float* text   = (const float*)d_in[1];
    const float* W      = (const float*)d_in[2];
    const float* bvec   = (const float*)d_in[3];
    const float* gate_w = (const float*)d_in[4];
    const float* gate_b = (const float*)d_in[5];
    const float* gnn_w  = (const float*)d_in[6];
    const float* gnn_b  = (const float*)d_in[7];
    const float* text_w = (const float*)d_in[8];
    const float* text_b = (const float*)d_in[9];
    const float* in_w   = (const float*)d_in[10];
    const float* in_b   = (const float*)d_in[11];
    const float* aow    = (const float*)d_in[12];
    const float* aob    = (const float*)d_in[13];
    const float* fgw    = (const float*)d_in[14];
    const float* fgb    = (const float*)d_in[15];
    const float* outp_w = (const float*)d_in[16];
    const float* outp_b = (const float*)d_in[17];
    const int*   en     = (const int*)d_in[18];
    float* outp = (float*)d_out;

    static bool attr_done = false;
    if (!attr_done) {
        cudaFuncSetAttribute(tgemm<1>, cudaFuncAttributeMaxDynamicSharedMemorySize, SMEM_BYTES);
        cudaFuncSetAttribute(tgemm<2>, cudaFuncAttributeMaxDynamicSharedMemorySize, SMEM_BYTES);
        cudaFuncSetAttribute(tgemm<3>, cudaFuncAttributeMaxDynamicSharedMemorySize, SMEM_BYTES);
        attr_done = true;
    }

    k_zero<<<32, 256>>>();
    k_alpha_part<<<256, 256>>>(x, gate_w);
    k_alpha_fin<<<1, 256>>>(gate_b);

    // Wg = W @ gnn_w, bg = b @ gnn_w + gnn_b
    k_prec<<<DD + 1, 128>>>(W, gnn_w, gnn_b, bvec);

    // hypergraph propagation on x
    k_edge_a<<<EE / 256, 256>>>(en);
    k_scan<<<1, 256>>>();
    k_fill<<<EE / 256, 256>>>(en);
    k_sort<<<NN / 256, 256>>>();
    k_edge_b<<<EE, 64>>>(en, x);
    k_gather<<<NN, 64>>>(x);

    // per-batch attention constants
    k_const<<<BB, 128>>>(text, text_w, text_b, in_w, in_b, aow, aob, fgw, fgb);

    // gp = z @ Wg + bg
    tgemm<1><<<dim3(2, 64), 256, SMEM_BYTES>>>(nullptr, nullptr, nullptr);

    // fused = sigmoid(gp @ fgate_w0 + c[b]) * gp + (1-g) * att[b]
    tgemm<2><<<dim3(2, 64), 256, SMEM_BYTES>>>(fgw, nullptr, nullptr);

    // result = fused @ outp_w + outp_b
    tgemm<3><<<dim3(4, 64), 256, SMEM_BYTES>>>(outp_w, outp, outp_b);
}